// round 2
// baseline (speedup 1.0000x reference)
#include <cuda_runtime.h>
#include <cstddef>

#define BDIM 128
#define LDIM 512
#define EHD  256
#define DHD  256
#define YD   8

// ---------------- device scratch (static, allocation-free) ----------------
__device__ float g_projx[(size_t)BDIM * LDIM * EHD];  // 64MB: x @ W1x^T
__device__ float g_u[BDIM * EHD];                     // per-step h/c projection
__device__ float g_h[2][BDIM * DHD];
__device__ float g_c[2][BDIM * DHD];
__device__ float g_yp[2][BDIM * YD];
__device__ float g_ctx[BDIM * EHD];
__device__ float g_yt[BDIM * YD];

// ---------------- math helpers ----------------
__device__ __forceinline__ float fast_tanh(float x) {
    // accurate to ~1e-6, 2 MUFU (EX2 + RCP). Robust at +-inf.
    float e = __expf(2.0f * x);
    return 1.0f - __fdividef(2.0f, e + 1.0f);
}
__device__ __forceinline__ float fast_sig(float x) {
    return __fdividef(1.0f, 1.0f + __expf(-x));
}
__device__ __forceinline__ float warp_sum(float v) {
    #pragma unroll
    for (int o = 16; o > 0; o >>= 1) v += __shfl_xor_sync(0xffffffffu, v, o);
    return v;
}
__device__ __forceinline__ float warp_max(float v) {
    #pragma unroll
    for (int o = 16; o > 0; o >>= 1) v = fmaxf(v, __shfl_xor_sync(0xffffffffu, v, o));
    return v;
}

// ---------------- init: h0=c0=0, y_prev0 = y_history_last ----------------
__global__ void k_init(const float* __restrict__ yh) {
    int i = blockIdx.x * blockDim.x + threadIdx.x;
    if (i < BDIM * DHD) { g_h[0][i] = 0.0f; g_c[0][i] = 0.0f; }
    if (i < BDIM * YD)  { g_yp[0][i] = yh[i]; }
}

// ---------------- proj_x GEMM: C[BL,256] = A[BL,256] * W1x^T ----------------
// W1x[n][k] = W_attn1[n*768 + 512 + k]. 128x128 tile, 8x8 per thread.
__global__ __launch_bounds__(256, 2) void k_projx(const float* __restrict__ A,
                                                  const float* __restrict__ W1) {
    __shared__ float As[16][132];
    __shared__ float Bs[16][132];
    const int bm = blockIdx.y * 128;
    const int bn = blockIdx.x * 128;
    const int tid = threadIdx.x;
    const int tx = tid & 15, ty = tid >> 4;
    const int r  = tid >> 2;           // 0..63
    const int c4 = (tid & 3) << 2;     // 0,4,8,12

    float acc[8][8];
    #pragma unroll
    for (int i = 0; i < 8; i++)
        #pragma unroll
        for (int j = 0; j < 8; j++) acc[i][j] = 0.0f;

    for (int k0 = 0; k0 < 256; k0 += 16) {
        float4 a0 = *(const float4*)(A  + (size_t)(bm + r)      * 256 + k0 + c4);
        float4 a1 = *(const float4*)(A  + (size_t)(bm + r + 64) * 256 + k0 + c4);
        float4 b0 = *(const float4*)(W1 + (size_t)(bn + r)      * 768 + 512 + k0 + c4);
        float4 b1 = *(const float4*)(W1 + (size_t)(bn + r + 64) * 768 + 512 + k0 + c4);
        __syncthreads();
        As[c4 + 0][r] = a0.x; As[c4 + 1][r] = a0.y; As[c4 + 2][r] = a0.z; As[c4 + 3][r] = a0.w;
        As[c4 + 0][r + 64] = a1.x; As[c4 + 1][r + 64] = a1.y; As[c4 + 2][r + 64] = a1.z; As[c4 + 3][r + 64] = a1.w;
        Bs[c4 + 0][r] = b0.x; Bs[c4 + 1][r] = b0.y; Bs[c4 + 2][r] = b0.z; Bs[c4 + 3][r] = b0.w;
        Bs[c4 + 0][r + 64] = b1.x; Bs[c4 + 1][r + 64] = b1.y; Bs[c4 + 2][r + 64] = b1.z; Bs[c4 + 3][r + 64] = b1.w;
        __syncthreads();
        #pragma unroll
        for (int kk = 0; kk < 16; kk++) {
            float af[8], bf[8];
            #pragma unroll
            for (int i = 0; i < 8; i++) af[i] = As[kk][ty * 8 + i];
            #pragma unroll
            for (int j = 0; j < 8; j++) bf[j] = Bs[kk][tx * 8 + j];
            #pragma unroll
            for (int i = 0; i < 8; i++)
                #pragma unroll
                for (int j = 0; j < 8; j++) acc[i][j] += af[i] * bf[j];
        }
    }
    #pragma unroll
    for (int i = 0; i < 8; i++) {
        size_t off = (size_t)(bm + ty * 8 + i) * 256 + bn + tx * 8;
        float4 v0 = make_float4(acc[i][0], acc[i][1], acc[i][2], acc[i][3]);
        float4 v1 = make_float4(acc[i][4], acc[i][5], acc[i][6], acc[i][7]);
        *(float4*)(g_projx + off)     = v0;
        *(float4*)(g_projx + off + 4) = v1;
    }
}

// ---------------- per-step u[b][j] = b1[j] + W1h[j,:].h[b] + W1c[j,:].c[b] ----
// grid (16 j-chunks, 8 b-chunks of 16), 256 threads. W rows staged in smem once.
__global__ __launch_bounds__(256) void k_u(const float* __restrict__ W1,
                                           const float* __restrict__ b1, int cur) {
    __shared__ float Ws[16][513];
    const int j0 = blockIdx.x * 16;
    const int b0 = blockIdx.y * 16;
    const int tid = threadIdx.x;

    for (int idx = tid; idx < 16 * 128; idx += 256) {   // 16 rows x 128 float4
        int row = idx >> 7;
        int col = (idx & 127) << 2;
        float4 v = *(const float4*)(W1 + (size_t)(j0 + row) * 768 + col);
        Ws[row][col + 0] = v.x; Ws[row][col + 1] = v.y;
        Ws[row][col + 2] = v.z; Ws[row][col + 3] = v.w;
    }
    __syncthreads();

    const int jl = tid & 15, bl = tid >> 4;
    const int j = j0 + jl, b = b0 + bl;
    const float4* h4 = (const float4*)(g_h[cur] + b * DHD);
    const float4* c4 = (const float4*)(g_c[cur] + b * DHD);
    float s = b1[j];
    #pragma unroll 8
    for (int k4 = 0; k4 < 64; k4++) {
        float4 hv = h4[k4];
        float4 cv = c4[k4];
        int k = k4 << 2;
        s += Ws[jl][k] * hv.x + Ws[jl][k + 1] * hv.y + Ws[jl][k + 2] * hv.z + Ws[jl][k + 3] * hv.w;
        s += Ws[jl][256 + k] * cv.x + Ws[jl][257 + k] * cv.y + Ws[jl][258 + k] * cv.z + Ws[jl][259 + k] * cv.w;
    }
    g_u[b * EHD + j] = s;
}

// ---------------- fused attention: scores -> softmax -> context -> y_tilde ---
// one block per batch element b, 256 threads (8 warps).
__global__ __launch_bounds__(256) void k_attn(const float* __restrict__ x,
                                              const float* __restrict__ w2,
                                              const float* __restrict__ b2,
                                              const float* __restrict__ Wfc,
                                              const float* __restrict__ bfc,
                                              int cur) {
    __shared__ float u_s[EHD], w2_s[EHD], sc[LDIM], ctx_s[EHD];
    __shared__ float red1[8], red2[8];
    const int b = blockIdx.x;
    const int tid = threadIdx.x;
    const int w = tid >> 5, ln = tid & 31;

    u_s[tid]  = g_u[b * EHD + tid];
    w2_s[tid] = w2[tid];
    __syncthreads();

    const float b2v = b2[0];
    // --- scores: each warp handles l = w, w+8, ... (coalesced 128B reads) ---
    for (int l = w; l < LDIM; l += 8) {
        const float4* p = (const float4*)(g_projx + ((size_t)b * LDIM + l) * EHD);
        float4 v0 = p[ln];
        float4 v1 = p[32 + ln];
        int j0 = ln << 2;
        int j1 = 128 + (ln << 2);
        float s = w2_s[j0]     * fast_tanh(v0.x + u_s[j0])
                + w2_s[j0 + 1] * fast_tanh(v0.y + u_s[j0 + 1])
                + w2_s[j0 + 2] * fast_tanh(v0.z + u_s[j0 + 2])
                + w2_s[j0 + 3] * fast_tanh(v0.w + u_s[j0 + 3])
                + w2_s[j1]     * fast_tanh(v1.x + u_s[j1])
                + w2_s[j1 + 1] * fast_tanh(v1.y + u_s[j1 + 1])
                + w2_s[j1 + 2] * fast_tanh(v1.z + u_s[j1 + 2])
                + w2_s[j1 + 3] * fast_tanh(v1.w + u_s[j1 + 3]);
        s = warp_sum(s);
        if (ln == 0) sc[l] = s + b2v;
    }
    __syncthreads();

    // --- softmax over L=512 ---
    float m = fmaxf(sc[tid], sc[tid + 256]);
    m = warp_max(m);
    if (ln == 0) red1[w] = m;
    __syncthreads();
    float mx = red1[0];
    #pragma unroll
    for (int i = 1; i < 8; i++) mx = fmaxf(mx, red1[i]);

    float e0 = __expf(sc[tid] - mx);
    float e1 = __expf(sc[tid + 256] - mx);
    sc[tid] = e0; sc[tid + 256] = e1;
    float ssum = warp_sum(e0 + e1);
    if (ln == 0) red2[w] = ssum;
    __syncthreads();     // also makes sc[] (exp) writes visible
    float tot = red2[0] + red2[1] + red2[2] + red2[3] + red2[4] + red2[5] + red2[6] + red2[7];
    float rinv = __fdividef(1.0f, tot);

    // --- context[j] = rinv * sum_l e_l * x[b,l,j] (thread j = tid) ---
    const float* xb = x + (size_t)b * LDIM * EHD;
    float acc = 0.0f;
    #pragma unroll 4
    for (int l = 0; l < LDIM; l++) acc += sc[l] * xb[(size_t)l * EHD + tid];
    acc *= rinv;
    ctx_s[tid] = acc;
    g_ctx[b * EHD + tid] = acc;
    __syncthreads();

    // --- y_tilde[y] = b_fc[y] + Wfc[y,0:256].ctx + Wfc[y,256:264].y_prev ---
    const float* wr = Wfc + w * 264;
    float t = 0.0f;
    #pragma unroll
    for (int k = ln; k < 256; k += 32) t += wr[k] * ctx_s[k];
    t = warp_sum(t);
    if (ln == 0) {
        const float* yp = g_yp[cur] + b * YD;
        #pragma unroll
        for (int k = 0; k < 8; k++) t += wr[256 + k] * yp[k];
        g_yt[b * YD + w] = t + bfc[w];
    }
}

// ---------------- gates + LSTM cell update ----------------
// grid (32 j-chunks of 8, 16 b-chunks of 8). Block stages 32 W_hh rows
// (4 gates x 8 j) in smem; each thread computes one gate pre-activation.
__global__ __launch_bounds__(256) void k_lstm(const float* __restrict__ Whh,
                                              const float* __restrict__ Wih,
                                              const float* __restrict__ bih,
                                              const float* __restrict__ bhh,
                                              int cur, int nxt) {
    __shared__ float Ws[32][257];
    __shared__ float Wi_s[32][9];
    __shared__ float bias_s[32];
    __shared__ float gv[4][64];
    const int j0 = blockIdx.x * 8;
    const int b0 = blockIdx.y * 8;
    const int tid = threadIdx.x;

    for (int idx = tid; idx < 32 * 64; idx += 256) {   // 32 rows x 64 float4
        int row = idx >> 6;
        int col = (idx & 63) << 2;
        int g = (row >> 3) * 256 + j0 + (row & 7);
        float4 v = *(const float4*)(Whh + (size_t)g * 256 + col);
        Ws[row][col + 0] = v.x; Ws[row][col + 1] = v.y;
        Ws[row][col + 2] = v.z; Ws[row][col + 3] = v.w;
    }
    {
        int row = tid >> 3, k = tid & 7;               // 256 = 32x8
        int g = (row >> 3) * 256 + j0 + (row & 7);
        Wi_s[row][k] = Wih[(size_t)g * 8 + k];
        if (tid < 32) {
            int gg = (tid >> 3) * 256 + j0 + (tid & 7);
            bias_s[tid] = bih[gg] + bhh[gg];
        }
    }
    __syncthreads();

    const int jl = tid & 7;
    const int bl = (tid >> 3) & 7;
    const int gate = tid >> 6;
    const int b = b0 + bl;
    const int row = gate * 8 + jl;

    const float4* h4 = (const float4*)(g_h[cur] + b * DHD);
    float s = bias_s[row];
    #pragma unroll 8
    for (int k4 = 0; k4 < 64; k4++) {
        float4 hv = h4[k4];
        int k = k4 << 2;
        s += Ws[row][k] * hv.x + Ws[row][k + 1] * hv.y + Ws[row][k + 2] * hv.z + Ws[row][k + 3] * hv.w;
    }
    const float* yt = g_yt + b * YD;
    #pragma unroll
    for (int k = 0; k < 8; k++) s += Wi_s[row][k] * yt[k];
    gv[gate][(bl << 3) | jl] = s;
    __syncthreads();

    if (tid < 64) {
        int jj = tid & 7, bb = tid >> 3;
        int gb = b0 + bb, gj = j0 + jj;
        float ig = gv[0][tid], fg = gv[1][tid], gg = gv[2][tid], og = gv[3][tid];
        float cold = g_c[cur][gb * DHD + gj];
        float cn = fast_sig(fg) * cold + fast_sig(ig) * fast_tanh(gg);
        float hn = fast_sig(og) * fast_tanh(cn);
        g_c[nxt][gb * DHD + gj] = cn;
        g_h[nxt][gb * DHD + gj] = hn;
    }
}

// ---------------- y_pred = [h_new, context] @ W_fin^T + b_fin ----------------
__global__ __launch_bounds__(256) void k_ypred(const float* __restrict__ Wfin,
                                               const float* __restrict__ bfin,
                                               float* __restrict__ out,
                                               int T, int t, int nxt) {
    const int b = blockIdx.x;
    const int w = threadIdx.x >> 5, ln = threadIdx.x & 31;
    const float* wr = Wfin + w * 512;
    const float* h  = g_h[nxt] + b * DHD;
    const float* cx = g_ctx + b * EHD;
    float s = 0.0f;
    #pragma unroll
    for (int k = ln; k < 256; k += 32) s += wr[k] * h[k] + wr[256 + k] * cx[k];
    s = warp_sum(s);
    if (ln == 0) {
        float v = s + bfin[w];
        out[((size_t)b * T + t) * YD + w] = v;
        g_yp[nxt][b * YD + w] = v;
    }
}

// ---------------- launch ----------------
extern "C" void kernel_launch(void* const* d_in, const int* in_sizes, int n_in,
                              void* d_out, int out_size) {
    const float* x    = (const float*)d_in[0];
    const float* yh   = (const float*)d_in[1];
    const float* W1   = (const float*)d_in[2];
    const float* b1   = (const float*)d_in[3];
    const float* w2   = (const float*)d_in[4];
    const float* b2   = (const float*)d_in[5];
    const float* Wih  = (const float*)d_in[6];
    const float* Whh  = (const float*)d_in[7];
    const float* bih  = (const float*)d_in[8];
    const float* bhh  = (const float*)d_in[9];
    const float* Wfc  = (const float*)d_in[10];
    const float* bfc  = (const float*)d_in[11];
    const float* Wfin = (const float*)d_in[12];
    const float* bfin = (const float*)d_in[13];
    float* out = (float*)d_out;

    const int T = out_size / (BDIM * YD);   // = fc_horizon (24)

    k_init<<<BDIM, 256>>>(yh);
    k_projx<<<dim3(2, 512), 256>>>(x, W1);

    for (int t = 0; t < T; t++) {
        int cur = t & 1, nxt = cur ^ 1;
        k_u<<<dim3(16, 8), 256>>>(W1, b1, cur);
        k_attn<<<BDIM, 256>>>(x, w2, b2, Wfc, bfc, cur);
        k_lstm<<<dim3(32, 16), 256>>>(Whh, Wih, bih, bhh, cur, nxt);
        k_ypred<<<BDIM, 256>>>(Wfin, bfin, out, T, t, nxt);
    }
}

// round 5
// speedup vs baseline: 2.5702x; 2.5702x over previous
#include <cuda_runtime.h>
#include <cuda_bf16.h>
#include <cstddef>
#include <cstdint>

#define BDIM 128
#define LDIM 512
#define EHD  256
#define DHD  256
#define YD   8
#define NS   4          // L-chunks for flash context
#define LCH  (LDIM/NS)  // 128

// ---------------- device scratch (static, allocation-free) ----------------
__device__ __nv_bfloat16 g_projh[(size_t)BDIM * LDIM * EHD]; // 32MB bf16
__device__ float g_u[BDIM * EHD];
__device__ float g_h[2][BDIM * DHD];
__device__ float g_c[2][BDIM * DHD];
__device__ float g_yp[2][BDIM * YD];
__device__ float g_ctx[BDIM * EHD];
__device__ float g_yt[BDIM * YD];
__device__ float g_pctx[BDIM * NS * EHD];
__device__ float g_ms[BDIM * NS * 2];   // (max, sum) per chunk

// ---------------- math helpers ----------------
__device__ __forceinline__ float tanh_hw(float x) {   // sm_75+ HW tanh, ~1e-3 abs
    float y; asm("tanh.approx.f32 %0, %1;" : "=f"(y) : "f"(x)); return y;
}
__device__ __forceinline__ float fast_tanh(float x) { // accurate (~1e-6), for LSTM
    float e = __expf(2.0f * x);
    return 1.0f - __fdividef(2.0f, e + 1.0f);
}
__device__ __forceinline__ float fast_sig(float x) {
    return __fdividef(1.0f, 1.0f + __expf(-x));
}
__device__ __forceinline__ float warp_sum(float v) {
    #pragma unroll
    for (int o = 16; o > 0; o >>= 1) v += __shfl_xor_sync(0xffffffffu, v, o);
    return v;
}
__device__ __forceinline__ float warp_max(float v) {
    #pragma unroll
    for (int o = 16; o > 0; o >>= 1) v = fmaxf(v, __shfl_xor_sync(0xffffffffu, v, o));
    return v;
}

// ---------------- init ----------------
__global__ void k_init(const float* __restrict__ yh) {
    int i = blockIdx.x * blockDim.x + threadIdx.x;
    if (i < BDIM * DHD) { g_h[0][i] = 0.0f; g_c[0][i] = 0.0f; }
    if (i < BDIM * YD)  { g_yp[0][i] = yh[i]; }
}

// ---------------- proj_x GEMM: bf16 out. C[BL,256] = A[BL,256] * W1x^T -------
__global__ __launch_bounds__(256, 2) void k_projx(const float* __restrict__ A,
                                                  const float* __restrict__ W1) {
    __shared__ float As[16][132];
    __shared__ float Bs[16][132];
    const int bm = blockIdx.y * 128;
    const int bn = blockIdx.x * 128;
    const int tid = threadIdx.x;
    const int tx = tid & 15, ty = tid >> 4;
    const int r  = tid >> 2;
    const int c4 = (tid & 3) << 2;

    float acc[8][8];
    #pragma unroll
    for (int i = 0; i < 8; i++)
        #pragma unroll
        for (int j = 0; j < 8; j++) acc[i][j] = 0.0f;

    for (int k0 = 0; k0 < 256; k0 += 16) {
        float4 a0 = *(const float4*)(A  + (size_t)(bm + r)      * 256 + k0 + c4);
        float4 a1 = *(const float4*)(A  + (size_t)(bm + r + 64) * 256 + k0 + c4);
        float4 b0 = *(const float4*)(W1 + (size_t)(bn + r)      * 768 + 512 + k0 + c4);
        float4 b1 = *(const float4*)(W1 + (size_t)(bn + r + 64) * 768 + 512 + k0 + c4);
        __syncthreads();
        As[c4 + 0][r] = a0.x; As[c4 + 1][r] = a0.y; As[c4 + 2][r] = a0.z; As[c4 + 3][r] = a0.w;
        As[c4 + 0][r + 64] = a1.x; As[c4 + 1][r + 64] = a1.y; As[c4 + 2][r + 64] = a1.z; As[c4 + 3][r + 64] = a1.w;
        Bs[c4 + 0][r] = b0.x; Bs[c4 + 1][r] = b0.y; Bs[c4 + 2][r] = b0.z; Bs[c4 + 3][r] = b0.w;
        Bs[c4 + 0][r + 64] = b1.x; Bs[c4 + 1][r + 64] = b1.y; Bs[c4 + 2][r + 64] = b1.z; Bs[c4 + 3][r + 64] = b1.w;
        __syncthreads();
        #pragma unroll
        for (int kk = 0; kk < 16; kk++) {
            float af[8], bf[8];
            #pragma unroll
            for (int i = 0; i < 8; i++) af[i] = As[kk][ty * 8 + i];
            #pragma unroll
            for (int j = 0; j < 8; j++) bf[j] = Bs[kk][tx * 8 + j];
            #pragma unroll
            for (int i = 0; i < 8; i++)
                #pragma unroll
                for (int j = 0; j < 8; j++) acc[i][j] += af[i] * bf[j];
        }
    }
    #pragma unroll
    for (int i = 0; i < 8; i++) {
        size_t off = (size_t)(bm + ty * 8 + i) * 256 + bn + tx * 8;
        __nv_bfloat162 tmp[4];
        tmp[0] = __floats2bfloat162_rn(acc[i][0], acc[i][1]);
        tmp[1] = __floats2bfloat162_rn(acc[i][2], acc[i][3]);
        tmp[2] = __floats2bfloat162_rn(acc[i][4], acc[i][5]);
        tmp[3] = __floats2bfloat162_rn(acc[i][6], acc[i][7]);
        *(uint4*)(g_projh + off) = *(uint4*)tmp;
    }
}

// ---------------- merged head: u(t) and y_pred(t-1) --------------------------
// grid (16, 9): by<8 -> u blocks (j0=bx*16, b0=by*16); by==8 -> ypred blocks.
__global__ __launch_bounds__(256) void k_head(const float* __restrict__ W1,
                                              const float* __restrict__ b1,
                                              const float* __restrict__ Wfin,
                                              const float* __restrict__ bfin,
                                              float* __restrict__ out,
                                              int T, int t, int cur,
                                              int do_u, int do_yp) {
    __shared__ float Ws[16][513];
    const int tid = threadIdx.x;

    if (blockIdx.y == 8) {
        // ---- y_pred for step t-1 ----
        if (!do_yp) return;
        const int w = tid >> 5, ln = tid & 31;
        const int b = blockIdx.x * 8 + w;
        const float* h  = g_h[cur] + b * DHD;
        const float* cx = g_ctx + b * EHD;
        #pragma unroll
        for (int y = 0; y < YD; y++) {
            const float* wr = Wfin + y * 512;
            float s = 0.0f;
            #pragma unroll
            for (int k = ln; k < 256; k += 32) s += wr[k] * h[k] + wr[256 + k] * cx[k];
            s = warp_sum(s);
            if (ln == 0) {
                float v = s + bfin[y];
                out[((size_t)b * T + (t - 1)) * YD + y] = v;
                g_yp[cur][b * YD + y] = v;
            }
        }
        return;
    }

    // ---- u[b][j] = b1[j] + W1h[j,:].h + W1c[j,:].c ----
    if (!do_u) return;
    const int j0 = blockIdx.x * 16;
    const int b0 = blockIdx.y * 16;

    for (int idx = tid; idx < 16 * 128; idx += 256) {
        int row = idx >> 7;
        int col = (idx & 127) << 2;
        float4 v = *(const float4*)(W1 + (size_t)(j0 + row) * 768 + col);
        Ws[row][col + 0] = v.x; Ws[row][col + 1] = v.y;
        Ws[row][col + 2] = v.z; Ws[row][col + 3] = v.w;
    }
    __syncthreads();

    const int jl = tid & 15, bl = tid >> 4;
    const int j = j0 + jl, b = b0 + bl;
    const float4* h4 = (const float4*)(g_h[cur] + b * DHD);
    const float4* c4 = (const float4*)(g_c[cur] + b * DHD);
    float s = b1[j];
    #pragma unroll 8
    for (int k4 = 0; k4 < 64; k4++) {
        float4 hv = h4[k4];
        float4 cv = c4[k4];
        int k = k4 << 2;
        s += Ws[jl][k] * hv.x + Ws[jl][k + 1] * hv.y + Ws[jl][k + 2] * hv.z + Ws[jl][k + 3] * hv.w;
        s += Ws[jl][256 + k] * cv.x + Ws[jl][257 + k] * cv.y + Ws[jl][258 + k] * cv.z + Ws[jl][259 + k] * cv.w;
    }
    g_u[b * EHD + j] = s;
}

// ---------------- flash scores + chunk softmax + partial context -------------
// grid (B, NS), 256 threads. Chunk c handles l in [c*128, c*128+128).
__global__ __launch_bounds__(256) void k_fctx(const float* __restrict__ x,
                                              const float* __restrict__ w2) {
    __shared__ float u_s[EHD], w2_s[EHD], sc[LCH], red[8];
    const int b = blockIdx.x;
    const int c = blockIdx.y;
    const int l0 = c * LCH;
    const int tid = threadIdx.x;
    const int w = tid >> 5, ln = tid & 31;

    u_s[tid]  = g_u[b * EHD + tid];
    w2_s[tid] = w2[tid];
    __syncthreads();

    // scores: warp w handles 16 l values
    const int j0 = ln << 3;
    const float uw0 = u_s[j0],     uw1 = u_s[j0 + 1], uw2 = u_s[j0 + 2], uw3 = u_s[j0 + 3];
    const float uw4 = u_s[j0 + 4], uw5 = u_s[j0 + 5], uw6 = u_s[j0 + 6], uw7 = u_s[j0 + 7];
    const float w20 = w2_s[j0],     w21 = w2_s[j0 + 1], w22 = w2_s[j0 + 2], w23 = w2_s[j0 + 3];
    const float w24 = w2_s[j0 + 4], w25 = w2_s[j0 + 5], w26 = w2_s[j0 + 6], w27 = w2_s[j0 + 7];
    for (int li = 0; li < 16; li++) {
        int l = w * 16 + li;
        const uint4* p = (const uint4*)(g_projh + ((size_t)(b * LDIM + l0 + l)) * EHD);
        uint4 pv = p[ln];
        float2 f0 = __bfloat1622float2(*(__nv_bfloat162*)&pv.x);
        float2 f1 = __bfloat1622float2(*(__nv_bfloat162*)&pv.y);
        float2 f2 = __bfloat1622float2(*(__nv_bfloat162*)&pv.z);
        float2 f3 = __bfloat1622float2(*(__nv_bfloat162*)&pv.w);
        float s = w20 * tanh_hw(f0.x + uw0) + w21 * tanh_hw(f0.y + uw1)
                + w22 * tanh_hw(f1.x + uw2) + w23 * tanh_hw(f1.y + uw3)
                + w24 * tanh_hw(f2.x + uw4) + w25 * tanh_hw(f2.y + uw5)
                + w26 * tanh_hw(f3.x + uw6) + w27 * tanh_hw(f3.y + uw7);
        s = warp_sum(s);
        if (ln == 0) sc[l] = s;
    }
    __syncthreads();

    // chunk max
    float v = (tid < LCH) ? sc[tid] : -1e30f;
    float m = warp_max(v);
    if (ln == 0) red[w] = m;
    __syncthreads();
    float mx = red[0];
    #pragma unroll
    for (int i = 1; i < 8; i++) mx = fmaxf(mx, red[i]);
    __syncthreads();

    // exps + chunk sum
    float e = 0.0f;
    if (tid < LCH) { e = __expf(sc[tid] - mx); sc[tid] = e; }
    float ssum = warp_sum(e);
    if (ln == 0) red[w] = ssum;
    __syncthreads();
    float stot = red[0] + red[1] + red[2] + red[3] + red[4] + red[5] + red[6] + red[7];

    // partial context over this chunk (unnormalized)
    const float* xb = x + ((size_t)(b * LDIM + l0)) * EHD + tid;
    float acc = 0.0f;
    #pragma unroll 4
    for (int l = 0; l < LCH; l++) acc += sc[l] * xb[(size_t)l * EHD];

    g_pctx[(b * NS + c) * EHD + tid] = acc;
    if (tid == 0) {
        g_ms[(b * NS + c) * 2 + 0] = mx;
        g_ms[(b * NS + c) * 2 + 1] = stot;
    }
}

// ---------------- combine partials -> context -> y_tilde ---------------------
__global__ __launch_bounds__(256) void k_ytilde(const float* __restrict__ Wfc,
                                                const float* __restrict__ bfc,
                                                int cur) {
    __shared__ float ctx_s[EHD];
    const int b = blockIdx.x;
    const int tid = threadIdx.x;
    const int w = tid >> 5, ln = tid & 31;

    float m0 = g_ms[(b * NS + 0) * 2], s0 = g_ms[(b * NS + 0) * 2 + 1];
    float m1 = g_ms[(b * NS + 1) * 2], s1 = g_ms[(b * NS + 1) * 2 + 1];
    float m2 = g_ms[(b * NS + 2) * 2], s2 = g_ms[(b * NS + 2) * 2 + 1];
    float m3 = g_ms[(b * NS + 3) * 2], s3 = g_ms[(b * NS + 3) * 2 + 1];
    float M = fmaxf(fmaxf(m0, m1), fmaxf(m2, m3));
    float w0 = __expf(m0 - M), w1 = __expf(m1 - M);
    float w2w = __expf(m2 - M), w3 = __expf(m3 - M);
    float denom = w0 * s0 + w1 * s1 + w2w * s2 + w3 * s3;
    float rinv = __fdividef(1.0f, denom);

    float ctx = (w0 * g_pctx[(b * NS + 0) * EHD + tid]
               + w1 * g_pctx[(b * NS + 1) * EHD + tid]
               + w2w * g_pctx[(b * NS + 2) * EHD + tid]
               + w3 * g_pctx[(b * NS + 3) * EHD + tid]) * rinv;
    ctx_s[tid] = ctx;
    g_ctx[b * EHD + tid] = ctx;
    __syncthreads();

    // y_tilde[y] = b_fc + Wfc[y,0:256].ctx + Wfc[y,256:264].y_prev
    const float* wr = Wfc + w * 264;
    float t = 0.0f;
    #pragma unroll
    for (int k = ln; k < 256; k += 32) t += wr[k] * ctx_s[k];
    t = warp_sum(t);
    if (ln == 0) {
        const float* yp = g_yp[cur] + b * YD;
        #pragma unroll
        for (int k = 0; k < 8; k++) t += wr[256 + k] * yp[k];
        g_yt[b * YD + w] = t + bfc[w];
    }
}

// ---------------- gates + LSTM cell update ----------------
__global__ __launch_bounds__(256) void k_lstm(const float* __restrict__ Whh,
                                              const float* __restrict__ Wih,
                                              const float* __restrict__ bih,
                                              const float* __restrict__ bhh,
                                              int cur, int nxt) {
    __shared__ float Ws[32][257];
    __shared__ float Wi_s[32][9];
    __shared__ float bias_s[32];
    __shared__ float gv[4][64];
    const int j0 = blockIdx.x * 8;
    const int b0 = blockIdx.y * 8;
    const int tid = threadIdx.x;

    for (int idx = tid; idx < 32 * 64; idx += 256) {
        int row = idx >> 6;
        int col = (idx & 63) << 2;
        int g = (row >> 3) * 256 + j0 + (row & 7);
        float4 v = *(const float4*)(Whh + (size_t)g * 256 + col);
        Ws[row][col + 0] = v.x; Ws[row][col + 1] = v.y;
        Ws[row][col + 2] = v.z; Ws[row][col + 3] = v.w;
    }
    {
        int row = tid >> 3, k = tid & 7;
        int g = (row >> 3) * 256 + j0 + (row & 7);
        Wi_s[row][k] = Wih[(size_t)g * 8 + k];
        if (tid < 32) {
            int gg = (tid >> 3) * 256 + j0 + (tid & 7);
            bias_s[tid] = bih[gg] + bhh[gg];
        }
    }
    __syncthreads();

    const int jl = tid & 7;
    const int bl = (tid >> 3) & 7;
    const int gate = tid >> 6;
    const int b = b0 + bl;
    const int row = gate * 8 + jl;

    const float4* h4 = (const float4*)(g_h[cur] + b * DHD);
    float s = bias_s[row];
    #pragma unroll 8
    for (int k4 = 0; k4 < 64; k4++) {
        float4 hv = h4[k4];
        int k = k4 << 2;
        s += Ws[row][k] * hv.x + Ws[row][k + 1] * hv.y + Ws[row][k + 2] * hv.z + Ws[row][k + 3] * hv.w;
    }
    const float* yt = g_yt + b * YD;
    #pragma unroll
    for (int k = 0; k < 8; k++) s += Wi_s[row][k] * yt[k];
    gv[gate][(bl << 3) | jl] = s;
    __syncthreads();

    if (tid < 64) {
        int jj = tid & 7, bb = tid >> 3;
        int gb = b0 + bb, gj = j0 + jj;
        float ig = gv[0][tid], fg = gv[1][tid], gg = gv[2][tid], og = gv[3][tid];
        float cold = g_c[cur][gb * DHD + gj];
        float cn = fast_sig(fg) * cold + fast_sig(ig) * fast_tanh(gg);
        float hn = fast_sig(og) * fast_tanh(cn);
        g_c[nxt][gb * DHD + gj] = cn;
        g_h[nxt][gb * DHD + gj] = hn;
    }
}

// ---------------- launch ----------------
extern "C" void kernel_launch(void* const* d_in, const int* in_sizes, int n_in,
                              void* d_out, int out_size) {
    const float* x    = (const float*)d_in[0];
    const float* yh   = (const float*)d_in[1];
    const float* W1   = (const float*)d_in[2];
    const float* b1   = (const float*)d_in[3];
    const float* w2   = (const float*)d_in[4];
    const float* b2   = (const float*)d_in[5];  (void)b2; // cancels in softmax
    const float* Wih  = (const float*)d_in[6];
    const float* Whh  = (const float*)d_in[7];
    const float* bih  = (const float*)d_in[8];
    const float* bhh  = (const float*)d_in[9];
    const float* Wfc  = (const float*)d_in[10];
    const float* bfc  = (const float*)d_in[11];
    const float* Wfin = (const float*)d_in[12];
    const float* bfin = (const float*)d_in[13];
    float* out = (float*)d_out;

    const int T = out_size / (BDIM * YD);

    k_init<<<BDIM, 256>>>(yh);
    k_projx<<<dim3(2, 512), 256>>>(x, W1);

    for (int t = 0; t < T; t++) {
        int cur = t & 1, nxt = cur ^ 1;
        k_head<<<dim3(16, 9), 256>>>(W1, b1, Wfin, bfin, out, T, t, cur, 1, t > 0);
        k_fctx<<<dim3(BDIM, NS), 256>>>(x, w2);
        k_ytilde<<<BDIM, 256>>>(Wfc, bfc, cur);
        k_lstm<<<dim3(32, 16), 256>>>(Whh, Wih, bih, bhh, cur, nxt);
    }
    // final y_pred (step T-1); h lives in g_h[T&1]
    k_head<<<dim3(16, 9), 256>>>(W1, b1, Wfin, bfin, out, T, T, T & 1, 0, 1);
}

// round 10
// speedup vs baseline: 3.6724x; 1.4288x over previous
#include <cuda_runtime.h>
#include <cuda_fp16.h>
#include <cstddef>
#include <cstdint>

#define BDIM 128
#define LDIM 512
#define EHD  256
#define DHD  256
#define YD   8
#define NS   4          // L-chunks for flash context
#define LCH  (LDIM/NS)  // 128

// ---------------- device scratch (static, allocation-free) ----------------
__device__ __half g_projh[(size_t)BDIM * LDIM * EHD]; // 32MB fp16 proj
__device__ __half g_xh[(size_t)BDIM * LDIM * EHD];    // 32MB fp16 x
__device__ __half g_wh[EHD * EHD];                    // W1x fp16 [n][k]
__device__ float g_u[BDIM * EHD];
__device__ float g_h[2][BDIM * DHD];
__device__ float g_c[2][BDIM * DHD];
__device__ float g_yp[2][BDIM * YD];
__device__ float g_ctx[BDIM * EHD];
__device__ float g_pctx[BDIM * NS * EHD];
__device__ float g_ms[BDIM * NS * 2];   // (max, sum) per chunk

// ---------------- math helpers ----------------
__device__ __forceinline__ float tanh_hw(float x) {
    float y; asm("tanh.approx.f32 %0, %1;" : "=f"(y) : "f"(x)); return y;
}
__device__ __forceinline__ float fast_tanh(float x) { // accurate, for LSTM
    float e = __expf(2.0f * x);
    return 1.0f - __fdividef(2.0f, e + 1.0f);
}
__device__ __forceinline__ float fast_sig(float x) {
    return __fdividef(1.0f, 1.0f + __expf(-x));
}
__device__ __forceinline__ float warp_sum(float v) {
    #pragma unroll
    for (int o = 16; o > 0; o >>= 1) v += __shfl_xor_sync(0xffffffffu, v, o);
    return v;
}
__device__ __forceinline__ float warp_max(float v) {
    #pragma unroll
    for (int o = 16; o > 0; o >>= 1) v = fmaxf(v, __shfl_xor_sync(0xffffffffu, v, o));
    return v;
}
__device__ __forceinline__ void mma_f16(float c[4], const uint32_t a[4],
                                        const uint32_t b[2]) {
    asm volatile(
        "mma.sync.aligned.m16n8k16.row.col.f32.f16.f16.f32 "
        "{%0,%1,%2,%3}, {%4,%5,%6,%7}, {%8,%9}, {%0,%1,%2,%3};\n"
        : "+f"(c[0]), "+f"(c[1]), "+f"(c[2]), "+f"(c[3])
        : "r"(a[0]), "r"(a[1]), "r"(a[2]), "r"(a[3]), "r"(b[0]), "r"(b[1]));
}

// ---------------- init + converts ----------------
__global__ void k_init(const float* __restrict__ yh) {
    int i = blockIdx.x * blockDim.x + threadIdx.x;
    if (i < BDIM * DHD) { g_h[0][i] = 0.0f; g_c[0][i] = 0.0f; }
    if (i < BDIM * YD)  { g_yp[0][i] = yh[i]; }
}

__global__ __launch_bounds__(256) void k_convx(const float* __restrict__ x) {
    // 16.8M floats = 4.19M float4
    const int n4 = (BDIM * LDIM * EHD) / 4;
    for (int i = blockIdx.x * blockDim.x + threadIdx.x; i < n4;
         i += gridDim.x * blockDim.x) {
        float4 v = *(const float4*)(x + (size_t)i * 4);
        __half2 p0 = __floats2half2_rn(v.x, v.y);
        __half2 p1 = __floats2half2_rn(v.z, v.w);
        uint2 o; o.x = *(uint32_t*)&p0; o.y = *(uint32_t*)&p1;
        *(uint2*)(g_xh + (size_t)i * 4) = o;
    }
}

__global__ __launch_bounds__(256) void k_convw(const float* __restrict__ W1) {
    // W1x[n][k] = W1[n*768 + 512 + k], 256x256 -> fp16
    int i = blockIdx.x * blockDim.x + threadIdx.x;   // 64 blocks x 256 = 16384 float4
    int row = i >> 6;
    int c4 = (i & 63) * 4;
    float4 v = *(const float4*)(W1 + (size_t)row * 768 + 512 + c4);
    __half2 p0 = __floats2half2_rn(v.x, v.y);
    __half2 p1 = __floats2half2_rn(v.z, v.w);
    uint2 o; o.x = *(uint32_t*)&p0; o.y = *(uint32_t*)&p1;
    *(uint2*)(g_wh + (size_t)row * 256 + c4) = o;
}

// ---------------- tensor-core proj GEMM --------------------------------------
// C[65536,256] = Xh[65536,256] @ Wh[256,256]^T, fp16 in, fp32 acc, fp16 out.
// Block 128x128, 8 warps (4m x 2n), warp tile 32x64. k staged in 4 chunks of 64.
__global__ __launch_bounds__(256) void k_projmma() {
    __shared__ __half As[128][72];
    __shared__ __half Bs[128][72];
    const int bm = blockIdx.y * 128;
    const int bn = blockIdx.x * 128;
    const int tid = threadIdx.x;
    const int wid = tid >> 5, ln = tid & 31;
    const int wm = wid & 3, wn = wid >> 2;
    const int g = ln >> 2, tg2 = (ln & 3) * 2;

    float acc[2][8][4];
    #pragma unroll
    for (int mi = 0; mi < 2; mi++)
        #pragma unroll
        for (int ni = 0; ni < 8; ni++)
            #pragma unroll
            for (int q = 0; q < 4; q++) acc[mi][ni][q] = 0.0f;

    for (int kc = 0; kc < 4; kc++) {
        const int kb = kc * 64;
        #pragma unroll
        for (int it = 0; it < 4; it++) {
            int idx = it * 256 + tid;          // 1024 uint4 per tile
            int row = idx >> 3;
            int col8 = (idx & 7) * 8;
            uint4 av = *(const uint4*)(g_xh + (size_t)(bm + row) * 256 + kb + col8);
            uint4 bv = *(const uint4*)(g_wh + (size_t)(bn + row) * 256 + kb + col8);
            *(uint4*)&As[row][col8] = av;
            *(uint4*)&Bs[row][col8] = bv;
        }
        __syncthreads();

        #pragma unroll
        for (int ks = 0; ks < 64; ks += 16) {
            uint32_t a[2][4], bf[8][2];
            #pragma unroll
            for (int mi = 0; mi < 2; mi++) {
                int mb = wm * 32 + mi * 16;
                a[mi][0] = *(const uint32_t*)&As[mb + g][ks + tg2];
                a[mi][1] = *(const uint32_t*)&As[mb + g + 8][ks + tg2];
                a[mi][2] = *(const uint32_t*)&As[mb + g][ks + tg2 + 8];
                a[mi][3] = *(const uint32_t*)&As[mb + g + 8][ks + tg2 + 8];
            }
            #pragma unroll
            for (int ni = 0; ni < 8; ni++) {
                int nb = wn * 64 + ni * 8;
                bf[ni][0] = *(const uint32_t*)&Bs[nb + g][ks + tg2];
                bf[ni][1] = *(const uint32_t*)&Bs[nb + g][ks + tg2 + 8];
            }
            #pragma unroll
            for (int mi = 0; mi < 2; mi++)
                #pragma unroll
                for (int ni = 0; ni < 8; ni++)
                    mma_f16(acc[mi][ni], a[mi], bf[ni]);
        }
        __syncthreads();
    }

    // store fp16
    #pragma unroll
    for (int mi = 0; mi < 2; mi++) {
        int r0 = bm + wm * 32 + mi * 16 + g;
        #pragma unroll
        for (int ni = 0; ni < 8; ni++) {
            int col = bn + wn * 64 + ni * 8 + tg2;
            __half2 p0 = __floats2half2_rn(acc[mi][ni][0], acc[mi][ni][1]);
            __half2 p1 = __floats2half2_rn(acc[mi][ni][2], acc[mi][ni][3]);
            *(uint32_t*)&g_projh[(size_t)r0 * 256 + col] = *(uint32_t*)&p0;
            *(uint32_t*)&g_projh[(size_t)(r0 + 8) * 256 + col] = *(uint32_t*)&p1;
        }
    }
}

// ---------------- merged head: u(t) and y_pred(t-1) --------------------------
__global__ __launch_bounds__(256) void k_head(const float* __restrict__ W1,
                                              const float* __restrict__ b1,
                                              const float* __restrict__ Wfin,
                                              const float* __restrict__ bfin,
                                              float* __restrict__ out,
                                              int T, int t, int cur,
                                              int do_u, int do_yp) {
    __shared__ float Ws[16][513];
    const int tid = threadIdx.x;

    if (blockIdx.y == 8) {
        if (!do_yp) return;
        const int w = tid >> 5, ln = tid & 31;
        const int b = blockIdx.x * 8 + w;
        const float* h  = g_h[cur] + b * DHD;
        const float* cx = g_ctx + b * EHD;
        #pragma unroll
        for (int y = 0; y < YD; y++) {
            const float* wr = Wfin + y * 512;
            float s = 0.0f;
            #pragma unroll
            for (int k = ln; k < 256; k += 32) s += wr[k] * h[k] + wr[256 + k] * cx[k];
            s = warp_sum(s);
            if (ln == 0) {
                float v = s + bfin[y];
                out[((size_t)b * T + (t - 1)) * YD + y] = v;
                g_yp[cur][b * YD + y] = v;
            }
        }
        return;
    }

    if (!do_u) return;
    const int j0 = blockIdx.x * 16;
    const int b0 = blockIdx.y * 16;

    for (int idx = tid; idx < 16 * 128; idx += 256) {
        int row = idx >> 7;
        int col = (idx & 127) << 2;
        float4 v = *(const float4*)(W1 + (size_t)(j0 + row) * 768 + col);
        Ws[row][col + 0] = v.x; Ws[row][col + 1] = v.y;
        Ws[row][col + 2] = v.z; Ws[row][col + 3] = v.w;
    }
    __syncthreads();

    const int jl = tid & 15, bl = tid >> 4;
    const int j = j0 + jl, b = b0 + bl;
    const float4* h4 = (const float4*)(g_h[cur] + b * DHD);
    const float4* c4 = (const float4*)(g_c[cur] + b * DHD);
    float s = b1[j];
    #pragma unroll 8
    for (int k4 = 0; k4 < 64; k4++) {
        float4 hv = h4[k4];
        float4 cv = c4[k4];
        int k = k4 << 2;
        s += Ws[jl][k] * hv.x + Ws[jl][k + 1] * hv.y + Ws[jl][k + 2] * hv.z + Ws[jl][k + 3] * hv.w;
        s += Ws[jl][256 + k] * cv.x + Ws[jl][257 + k] * cv.y + Ws[jl][258 + k] * cv.z + Ws[jl][259 + k] * cv.w;
    }
    g_u[b * EHD + j] = s;
}

// ---------------- flash scores + chunk softmax + partial context -------------
__global__ __launch_bounds__(256) void k_fctx(const float* __restrict__ w2) {
    __shared__ float u_s[EHD], w2_s[EHD], sc[LCH], red[8];
    __shared__ float part[2][EHD];
    const int b = blockIdx.x;
    const int c = blockIdx.y;
    const int l0 = c * LCH;
    const int tid = threadIdx.x;
    const int w = tid >> 5, ln = tid & 31;

    u_s[tid]  = g_u[b * EHD + tid];
    w2_s[tid] = w2[tid];
    __syncthreads();

    const int j0 = ln << 3;
    const float uw0 = u_s[j0],     uw1 = u_s[j0 + 1], uw2 = u_s[j0 + 2], uw3 = u_s[j0 + 3];
    const float uw4 = u_s[j0 + 4], uw5 = u_s[j0 + 5], uw6 = u_s[j0 + 6], uw7 = u_s[j0 + 7];
    const float w20 = w2_s[j0],     w21 = w2_s[j0 + 1], w22 = w2_s[j0 + 2], w23 = w2_s[j0 + 3];
    const float w24 = w2_s[j0 + 4], w25 = w2_s[j0 + 5], w26 = w2_s[j0 + 6], w27 = w2_s[j0 + 7];
    for (int li = 0; li < 16; li++) {
        int l = w * 16 + li;
        const uint4* p = (const uint4*)(g_projh + ((size_t)(b * LDIM + l0 + l)) * EHD);
        uint4 pv = p[ln];
        float2 f0 = __half22float2(*(__half2*)&pv.x);
        float2 f1 = __half22float2(*(__half2*)&pv.y);
        float2 f2 = __half22float2(*(__half2*)&pv.z);
        float2 f3 = __half22float2(*(__half2*)&pv.w);
        float s = w20 * tanh_hw(f0.x + uw0) + w21 * tanh_hw(f0.y + uw1)
                + w22 * tanh_hw(f1.x + uw2) + w23 * tanh_hw(f1.y + uw3)
                + w24 * tanh_hw(f2.x + uw4) + w25 * tanh_hw(f2.y + uw5)
                + w26 * tanh_hw(f3.x + uw6) + w27 * tanh_hw(f3.y + uw7);
        s = warp_sum(s);
        if (ln == 0) sc[l] = s;
    }
    __syncthreads();

    float v = (tid < LCH) ? sc[tid] : -1e30f;
    float m = warp_max(v);
    if (ln == 0) red[w] = m;
    __syncthreads();
    float mx = red[0];
    #pragma unroll
    for (int i = 1; i < 8; i++) mx = fmaxf(mx, red[i]);
    __syncthreads();

    float e = 0.0f;
    if (tid < LCH) { e = __expf(sc[tid] - mx); sc[tid] = e; }
    float ssum = warp_sum(e);
    if (ln == 0) red[w] = ssum;
    __syncthreads();
    float stot = red[0] + red[1] + red[2] + red[3] + red[4] + red[5] + red[6] + red[7];

    // partial context: half = tid>>7 covers 64 l's; each thread does j pair.
    const int half = tid >> 7;
    const int jp = (tid & 127) * 2;
    const __half* xb = g_xh + ((size_t)(b * LDIM + l0 + half * 64)) * EHD + jp;
    float a0 = 0.0f, a1 = 0.0f;
    #pragma unroll 4
    for (int l = 0; l < 64; l++) {
        uint32_t pv = *(const uint32_t*)(xb + (size_t)l * EHD);
        float2 f = __half22float2(*(__half2*)&pv);
        float wv = sc[half * 64 + l];
        a0 += wv * f.x; a1 += wv * f.y;
    }
    part[half][jp] = a0; part[half][jp + 1] = a1;
    __syncthreads();

    g_pctx[(b * NS + c) * EHD + tid] = part[0][tid] + part[1][tid];
    if (tid == 0) {
        g_ms[(b * NS + c) * 2 + 0] = mx;
        g_ms[(b * NS + c) * 2 + 1] = stot;
    }
}

// ---------------- combine + y_tilde + gates + LSTM cell ----------------------
// grid (32 j-chunks of 8, 16 b-chunks of 8), 256 threads.
__global__ __launch_bounds__(256) void k_lstm(const float* __restrict__ Whh,
                                              const float* __restrict__ Wih,
                                              const float* __restrict__ bih,
                                              const float* __restrict__ bhh,
                                              const float* __restrict__ Wfc,
                                              const float* __restrict__ bfc,
                                              int cur, int nxt) {
    __shared__ float Ws[32][257];
    __shared__ float Wi_s[32][9];
    __shared__ float bias_s[32];
    __shared__ float gv[4][64];
    __shared__ float ctx_s[8][EHD];
    __shared__ float yt_s[8][YD];
    const int j0 = blockIdx.x * 8;
    const int b0 = blockIdx.y * 8;
    const int tid = threadIdx.x;

    // stage Whh / Wih / bias
    for (int idx = tid; idx < 32 * 64; idx += 256) {
        int row = idx >> 6;
        int col = (idx & 63) << 2;
        int g = (row >> 3) * 256 + j0 + (row & 7);
        float4 v = *(const float4*)(Whh + (size_t)g * 256 + col);
        Ws[row][col + 0] = v.x; Ws[row][col + 1] = v.y;
        Ws[row][col + 2] = v.z; Ws[row][col + 3] = v.w;
    }
    {
        int row = tid >> 3, k = tid & 7;
        int g = (row >> 3) * 256 + j0 + (row & 7);
        Wi_s[row][k] = Wih[(size_t)g * 8 + k];
        if (tid < 32) {
            int gg = (tid >> 3) * 256 + j0 + (tid & 7);
            bias_s[tid] = bih[gg] + bhh[gg];
        }
    }

    // combine partial contexts (warp bb handles batch b0+bb)
    {
        const int bb = tid >> 5, ln = tid & 31;
        const int b = b0 + bb;
        float m0 = g_ms[(b * NS + 0) * 2], s0 = g_ms[(b * NS + 0) * 2 + 1];
        float m1 = g_ms[(b * NS + 1) * 2], s1 = g_ms[(b * NS + 1) * 2 + 1];
        float m2 = g_ms[(b * NS + 2) * 2], s2 = g_ms[(b * NS + 2) * 2 + 1];
        float m3 = g_ms[(b * NS + 3) * 2], s3 = g_ms[(b * NS + 3) * 2 + 1];
        float M = fmaxf(fmaxf(m0, m1), fmaxf(m2, m3));
        float e0 = __expf(m0 - M), e1 = __expf(m1 - M);
        float e2 = __expf(m2 - M), e3 = __expf(m3 - M);
        float rinv = __fdividef(1.0f, e0 * s0 + e1 * s1 + e2 * s2 + e3 * s3);
        #pragma unroll
        for (int i = 0; i < 8; i++) {
            int j = ln + i * 32;
            float cx = (e0 * g_pctx[(b * NS + 0) * EHD + j]
                      + e1 * g_pctx[(b * NS + 1) * EHD + j]
                      + e2 * g_pctx[(b * NS + 2) * EHD + j]
                      + e3 * g_pctx[(b * NS + 3) * EHD + j]) * rinv;
            ctx_s[bb][j] = cx;
            if (blockIdx.x == 0) g_ctx[b * EHD + j] = cx;
        }
    }
    __syncthreads();

    // y_tilde (warp bb computes 8 outputs for batch b0+bb)
    {
        const int bb = tid >> 5, ln = tid & 31;
        const int b = b0 + bb;
        #pragma unroll
        for (int y = 0; y < YD; y++) {
            const float* wr = Wfc + y * 264;
            float t = 0.0f;
            #pragma unroll
            for (int k = ln; k < 256; k += 32) t += wr[k] * ctx_s[bb][k];
            t = warp_sum(t);
            if (ln == 0) {
                const float* yp = g_yp[cur] + b * YD;
                #pragma unroll
                for (int k = 0; k < 8; k++) t += wr[256 + k] * yp[k];
                yt_s[bb][y] = t + bfc[y];
            }
        }
    }
    __syncthreads();

    // gates
    const int jl = tid & 7;
    const int bl = (tid >> 3) & 7;
    const int gate = tid >> 6;
    const int b = b0 + bl;
    const int row = gate * 8 + jl;

    const float4* h4 = (const float4*)(g_h[cur] + b * DHD);
    float s = bias_s[row];
    #pragma unroll 8
    for (int k4 = 0; k4 < 64; k4++) {
        float4 hv = h4[k4];
        int k = k4 << 2;
        s += Ws[row][k] * hv.x + Ws[row][k + 1] * hv.y + Ws[row][k + 2] * hv.z + Ws[row][k + 3] * hv.w;
    }
    #pragma unroll
    for (int k = 0; k < 8; k++) s += Wi_s[row][k] * yt_s[bl][k];
    gv[gate][(bl << 3) | jl] = s;
    __syncthreads();

    if (tid < 64) {
        int jj = tid & 7, bb = tid >> 3;
        int gb = b0 + bb, gj = j0 + jj;
        float ig = gv[0][tid], fg = gv[1][tid], gg = gv[2][tid], og = gv[3][tid];
        float cold = g_c[cur][gb * DHD + gj];
        float cn = fast_sig(fg) * cold + fast_sig(ig) * fast_tanh(gg);
        float hn = fast_sig(og) * fast_tanh(cn);
        g_c[nxt][gb * DHD + gj] = cn;
        g_h[nxt][gb * DHD + gj] = hn;
    }
}

// ---------------- launch ----------------
extern "C" void kernel_launch(void* const* d_in, const int* in_sizes, int n_in,
                              void* d_out, int out_size) {
    const float* x    = (const float*)d_in[0];
    const float* yh   = (const float*)d_in[1];
    const float* W1   = (const float*)d_in[2];
    const float* b1   = (const float*)d_in[3];
    const float* w2   = (const float*)d_in[4];
    const float* Wih  = (const float*)d_in[6];
    const float* Whh  = (const float*)d_in[7];
    const float* bih  = (const float*)d_in[8];
    const float* bhh  = (const float*)d_in[9];
    const float* Wfc  = (const float*)d_in[10];
    const float* bfc  = (const float*)d_in[11];
    const float* Wfin = (const float*)d_in[12];
    const float* bfin = (const float*)d_in[13];
    float* out = (float*)d_out;

    const int T = out_size / (BDIM * YD);

    k_init<<<BDIM, 256>>>(yh);
    k_convx<<<2048, 256>>>(x);
    k_convw<<<64, 256>>>(W1);
    k_projmma<<<dim3(2, 512), 256>>>();

    for (int t = 0; t < T; t++) {
        int cur = t & 1, nxt = cur ^ 1;
        k_head<<<dim3(16, 9), 256>>>(W1, b1, Wfin, bfin, out, T, t, cur, 1, t > 0);
        k_fctx<<<dim3(BDIM, NS), 256>>>(w2);
        k_lstm<<<dim3(32, 16), 256>>>(Whh, Wih, bih, bhh, Wfc, bfc, cur, nxt);
    }
    k_head<<<dim3(16, 9), 256>>>(W1, b1, Wfin, bfin, out, T, T, T & 1, 0, 1);
}